// round 16
// baseline (speedup 1.0000x reference)
#include <cuda_runtime.h>
#include <cuda_fp16.h>
#include <mma.h>

using namespace nvcuda;

// Problem constants (fixed by the dataset)
#define NNODES 50000
#define NEDGES 800000
#define DIN    256
#define DHID   128
#define DOUT   64
#define DEGCAP 128               // padded adjacency slots per node (P(overflow)<1e-60)
#define NODE_BLOCKS 196          // ceil(50000/256)
#define GEMM_BLOCKS 391          // ceil(50000/128)
#define EDGE_BLOCKS 782          // edge grid-stride blocks in the fused K2
#define ZOFF (NNODES * 128)      // byte offset of the always-zero feature row

// ---------------- static device scratch (no allocation allowed) --------------
__device__ __half g_hA[(NNODES + 1) * DOUT];   // feature ping (+ zero row)
__device__ __half g_hB[(NNODES + 1) * DOUT];   // feature pong (+ zero row)
__device__ __half g_hW13[DIN * DOUT];          // W1 @ W3, fp16
__device__ float  g_b13[DOUT];                 // b1 @ W3, fp32
__device__ int    g_deg_out[NNODES];
__device__ int    g_cursor[NNODES];            // slot counter; final value = in-degree
__device__ int    g_adj[NNODES * DEGCAP];      // padded adjacency: BYTE offsets (src*128)
__device__ float  g_ns[NNODES];
__device__ float  g_nd[NNODES];
__device__ float  g_nsd[NNODES];               // ns*nd (for bias-free props)

__device__ __forceinline__ __half2 H2(unsigned u) {
    return *reinterpret_cast<__half2*>(&u);
}

// ---------------- K1: zero counters + zero rows + fold W13/b13 ---------------
__global__ void __launch_bounds__(256) zero_w13_kernel(const float* __restrict__ W1,
                                                       const float* __restrict__ b1,
                                                       const float* __restrict__ W3) {
    int idx = blockIdx.x * 256 + threadIdx.x;
    if (idx < NNODES) { g_cursor[idx] = 0; g_deg_out[idx] = 0; }
    if (idx < DIN * DOUT) {
        int r = idx >> 6;
        int c = idx & 63;
        float s = 0.f;
#pragma unroll 8
        for (int k = 0; k < DHID; ++k)
            s = fmaf(W1[r * DHID + k], W3[k * DOUT + c], s);
        g_hW13[idx] = __float2half(s);
    }
    if (idx < DOUT) {
        float s = 0.f;
#pragma unroll 8
        for (int k = 0; k < DHID; ++k)
            s = fmaf(b1[k], W3[k * DOUT + idx], s);
        g_b13[idx] = s;
        // zero row NNODES of both feature buffers (gather target for padding;
        // never written by GEMM or props, so it stays zero all launch)
        ((unsigned short*)g_hA)[NNODES * DOUT + idx] = 0;
        ((unsigned short*)g_hB)[NNODES * DOUT + idx] = 0;
    }
}

// ---------------- K2: fused GEMM (X @ W13 -> fp16) ∥ edge pass ---------------
__global__ void __launch_bounds__(256)
gemm_edge_kernel(const float* __restrict__ A, __half* __restrict__ C,
                 const int* __restrict__ src, const int* __restrict__ dst) {
    if (blockIdx.x >= GEMM_BLOCKS) {
        const int stride = EDGE_BLOCKS * 256;
        int t = (blockIdx.x - GEMM_BLOCKS) * 256 + threadIdx.x;
        for (int e = t; e < NEDGES; e += stride) {
            int s = src[e];
            int d = dst[e];
            atomicAdd(&g_deg_out[s], 1);
            int p = atomicAdd(&g_cursor[d], 1);
            if (p < DEGCAP) g_adj[d * DEGCAP + p] = s << 7;   // byte offset: s*128
        }
        return;
    }

    // ---- GEMM path: block tile 128x64, BK=32, 8 warps (4x2 of 32x32) ----
    constexpr int M = NNODES, K = DIN, N = DOUT;
    constexpr int BK = 32;
    __shared__ __half As[128][BK + 8];
    __shared__ __half Bs[BK][N + 8];
    __shared__ float  Sepi[8][16 * 20];

    const int tid  = threadIdx.x;
    const int lane = tid & 31;
    const int wid  = tid >> 5;
    const int wm   = wid >> 1;
    const int wn   = wid & 1;
    const int blockRow = blockIdx.x * 128;

    wmma::fragment<wmma::accumulator, 16, 16, 16, float> facc[2][2];
#pragma unroll
    for (int i = 0; i < 2; ++i)
#pragma unroll
        for (int j = 0; j < 2; ++j) wmma::fill_fragment(facc[i][j], 0.0f);

    for (int k0 = 0; k0 < K; k0 += BK) {
#pragma unroll
        for (int l = 0; l < 4; ++l) {
            int idx = tid + l * 256;
            int r  = idx >> 3;
            int q  = idx & 7;
            int row = blockRow + r;
            float4 v = make_float4(0.f, 0.f, 0.f, 0.f);
            if (row < M) v = *(const float4*)&A[(long)row * K + k0 + q * 4];
            __half2 h0 = __floats2half2_rn(v.x, v.y);
            __half2 h1 = __floats2half2_rn(v.z, v.w);
            uint2 u;
            u.x = *reinterpret_cast<unsigned*>(&h0);
            u.y = *reinterpret_cast<unsigned*>(&h1);
            *(uint2*)&As[r][q * 4] = u;
        }
        {
            int r = tid >> 3;
            int q = tid & 7;
            uint4 u = *(const uint4*)&g_hW13[(k0 + r) * N + q * 8];
            *(uint4*)&Bs[r][q * 8] = u;
        }
        __syncthreads();

#pragma unroll
        for (int kk = 0; kk < BK; kk += 16) {
            wmma::fragment<wmma::matrix_a, 16, 16, 16, __half, wmma::row_major> fa[2];
            wmma::fragment<wmma::matrix_b, 16, 16, 16, __half, wmma::row_major> fb[2];
#pragma unroll
            for (int i = 0; i < 2; ++i)
                wmma::load_matrix_sync(fa[i], &As[wm * 32 + i * 16][kk], BK + 8);
#pragma unroll
            for (int j = 0; j < 2; ++j)
                wmma::load_matrix_sync(fb[j], &Bs[kk][wn * 32 + j * 16], N + 8);
#pragma unroll
            for (int i = 0; i < 2; ++i)
#pragma unroll
                for (int j = 0; j < 2; ++j)
                    wmma::mma_sync(facc[i][j], fa[i], fb[j], facc[i][j]);
        }
        __syncthreads();
    }

    float* scratch = Sepi[wid];
#pragma unroll
    for (int i = 0; i < 2; ++i) {
#pragma unroll
        for (int j = 0; j < 2; ++j) {
            wmma::store_matrix_sync(scratch, facc[i][j], 20, wmma::mem_row_major);
            __syncwarp();
            int r = lane >> 1;
            int c = (lane & 1) * 8;
            int gm = blockRow + wm * 32 + i * 16 + r;
            if (gm < M) {
                const float* p = &scratch[r * 20 + c];
                __half2 h0 = __floats2half2_rn(p[0], p[1]);
                __half2 h1 = __floats2half2_rn(p[2], p[3]);
                __half2 h2 = __floats2half2_rn(p[4], p[5]);
                __half2 h3 = __floats2half2_rn(p[6], p[7]);
                uint4 u;
                u.x = *reinterpret_cast<unsigned*>(&h0);
                u.y = *reinterpret_cast<unsigned*>(&h1);
                u.z = *reinterpret_cast<unsigned*>(&h2);
                u.w = *reinterpret_cast<unsigned*>(&h3);
                *(uint4*)&C[(long)gm * N + wn * 32 + j * 16 + c] = u;
            }
            __syncwarp();
        }
    }
}

// ---------------- K3: norms + pre-scale hA by ns + pad adj to mult-of-8 ------
__global__ void __launch_bounds__(256) norm_scale_kernel(__half2* __restrict__ hA2) {
    int node = (blockIdx.x * 256 + threadIdx.x) >> 5;
    int lane = threadIdx.x & 31;
    if (node >= NNODES) return;
    int deg = min(g_cursor[node], DEGCAP);
    int deg8 = (deg + 7) & ~7;
    // pad slots [deg, deg8) with the zero-row offset (exact-zero contributions)
    if (lane < deg8 - deg) g_adj[node * DEGCAP + deg + lane] = ZOFF;
    float ns = rsqrtf((float)max(g_deg_out[node], 1));
    float nd = rsqrtf((float)max(deg, 1));
    if (lane == 0) { g_ns[node] = ns; g_nd[node] = nd; g_nsd[node] = ns * nd; }
    __half2 nsh = __float2half2_rn(ns);
    int off = node * 32 + lane;
    hA2[off] = __hmul2(hA2[off], nsh);
}

// ---------------- propagation: 2 nodes per warp, 8 B per lane ----------------
// Lanes 0-15 -> node 2w, lanes 16-31 -> node 2w+1. Each lane gathers uint2
// (4 halves) so one LDG.64 warp-instruction retires one edge of EACH node
// (256 B/instr vs 128 B before). Adjacency padded to mult-of-8 with zero-row
// offsets: no 4-group, no scalar tail. fp16 depth-2 tree per 4 edges, fp32
// flush per 8. Input invariant: pre-scaled by ns.
//   BIAS && DO_NS : prop1  -> (acc*nd + b13) * ns, fp16 out
//   !BIAS && DO_NS: middle -> acc * nsd,           fp16 out
//   BIAS && !DO_NS: final  -> acc*nd + b3,         fp32 out
template <bool BIAS, bool DO_NS, bool FP32OUT>
__global__ void __launch_bounds__(256)
prop64_kernel(const __half2* __restrict__ in2, void* __restrict__ out,
              const float* __restrict__ bias) {
    const int warp = (blockIdx.x * blockDim.x + threadIdx.x) >> 5;
    const int lane = threadIdx.x & 31;
    const int l16  = lane & 15;
    const int node = warp * 2 + (lane >> 4);
    if (node >= NNODES) return;
    const int deg8 = (min(g_cursor[node], DEGCAP) + 7) & ~7;
    const int* __restrict__ adj = &g_adj[node * DEGCAP];
    const char* __restrict__ inb = (const char*)in2 + l16 * 8;   // per-lane base

    float4 acc = make_float4(0.f, 0.f, 0.f, 0.f);
    for (int e = 0; e < deg8; e += 8) {
        int4 a0 = *(const int4*)&adj[e];
        int4 a1 = *(const int4*)&adj[e + 4];
        uint2 v0 = __ldg((const uint2*)(inb + a0.x));
        uint2 v1 = __ldg((const uint2*)(inb + a0.y));
        uint2 v2 = __ldg((const uint2*)(inb + a0.z));
        uint2 v3 = __ldg((const uint2*)(inb + a0.w));
        uint2 v4 = __ldg((const uint2*)(inb + a1.x));
        uint2 v5 = __ldg((const uint2*)(inb + a1.y));
        uint2 v6 = __ldg((const uint2*)(inb + a1.z));
        uint2 v7 = __ldg((const uint2*)(inb + a1.w));
        // two depth-2 fp16 trees per component, fp32 flush
        __half2 g0lo = __hadd2(__hadd2(H2(v0.x), H2(v1.x)), __hadd2(H2(v2.x), H2(v3.x)));
        __half2 g0hi = __hadd2(__hadd2(H2(v0.y), H2(v1.y)), __hadd2(H2(v2.y), H2(v3.y)));
        __half2 g1lo = __hadd2(__hadd2(H2(v4.x), H2(v5.x)), __hadd2(H2(v6.x), H2(v7.x)));
        __half2 g1hi = __hadd2(__hadd2(H2(v4.y), H2(v5.y)), __hadd2(H2(v6.y), H2(v7.y)));
        float2 f0 = __half22float2(g0lo);
        float2 f1 = __half22float2(g0hi);
        float2 f2 = __half22float2(g1lo);
        float2 f3 = __half22float2(g1hi);
        acc.x += f0.x + f2.x;
        acc.y += f0.y + f2.y;
        acc.z += f1.x + f3.x;
        acc.w += f1.y + f3.y;
    }

    float4 o;
    if (BIAS) {
        float nd = g_nd[node];
        float4 bv = *(const float4*)&bias[l16 * 4];
        o.x = acc.x * nd + bv.x;
        o.y = acc.y * nd + bv.y;
        o.z = acc.z * nd + bv.z;
        o.w = acc.w * nd + bv.w;
        if (DO_NS) {
            float t = g_ns[node];
            o.x *= t; o.y *= t; o.z *= t; o.w *= t;
        }
    } else {
        float t = g_nsd[node];              // ns*nd folded
        o.x = acc.x * t; o.y = acc.y * t; o.z = acc.z * t; o.w = acc.w * t;
    }
    if (FP32OUT) {
        *(float4*)((float*)out + node * 64 + l16 * 4) = o;
    } else {
        __half2 h0 = __floats2half2_rn(o.x, o.y);
        __half2 h1 = __floats2half2_rn(o.z, o.w);
        uint2 u;
        u.x = *reinterpret_cast<unsigned*>(&h0);
        u.y = *reinterpret_cast<unsigned*>(&h1);
        ((uint2*)out)[node * 16 + l16] = u;
    }
}

// ---------------- launch -----------------------------------------------------
extern "C" void kernel_launch(void* const* d_in, const int* in_sizes, int n_in,
                              void* d_out, int out_size) {
    const float* X   = (const float*)d_in[0];
    const int*   src = (const int*)d_in[1];
    const int*   dst = (const int*)d_in[2];
    const float* W1  = (const float*)d_in[3];
    const float* b1  = (const float*)d_in[4];
    const float* W3  = (const float*)d_in[5];
    const float* b3  = (const float*)d_in[6];
    float* out = (float*)d_out;

    __half *hA, *hB;
    float *b13p;
    cudaGetSymbolAddress((void**)&hA,   g_hA);
    cudaGetSymbolAddress((void**)&hB,   g_hB);
    cudaGetSymbolAddress((void**)&b13p, g_b13);

    const int TPB = 256;
    const int scaleGrid = (NNODES * 32 + TPB - 1) / TPB;        // warp per node
    const int propGrid  = ((NNODES / 2) * 32 + TPB - 1) / TPB;  // warp per node PAIR

    // K1: zero counters + zero rows + fold W13/b13
    zero_w13_kernel<<<NODE_BLOCKS, TPB>>>(W1, b1, W3);

    // K2: GEMM (hA = fp16(X @ W13)) overlapped with the full edge pass
    gemm_edge_kernel<<<GEMM_BLOCKS + EDGE_BLOCKS, TPB>>>(X, hA, src, dst);

    // K3: norms (+nsd) + pre-scale hA rows by ns + pad adjacency to mult-of-8
    norm_scale_kernel<<<scaleGrid, TPB>>>((__half2*)hA);

    // six propagations at D=64 (two nodes per warp):
    prop64_kernel<true,  true,  false><<<propGrid, TPB>>>((const __half2*)hA, hB, b13p);
    prop64_kernel<false, true,  false><<<propGrid, TPB>>>((const __half2*)hB, hA, nullptr);
    prop64_kernel<false, true,  false><<<propGrid, TPB>>>((const __half2*)hA, hB, nullptr);
    prop64_kernel<false, true,  false><<<propGrid, TPB>>>((const __half2*)hB, hA, nullptr);
    prop64_kernel<false, true,  false><<<propGrid, TPB>>>((const __half2*)hA, hB, nullptr);
    prop64_kernel<true,  false, true ><<<propGrid, TPB>>>((const __half2*)hB, out, b3);
}